// round 15
// baseline (speedup 1.0000x reference)
#include <cuda_runtime.h>
#include <cuda_fp16.h>
#include <cstdint>
#include <cstddef>

// Problem dims
#define NQ 8192
#define MC 20000
#define MP 20096            // centers padded: 157*128
#define DD 1024
#define YY 256
#define PADW 20             // smem row stride words (conflict-free)

// GEMM1 heterogeneous tiling: 128 tensor rows + 64 SIMT rows per CTA
#define BMT 128
#define BMS 64
#define BMALL 192
#define BN1 128
#define ROWW 20
#define AW (BMALL * ROWW)             // 3840 words
#define BW (BN1 * ROWW)               // 2560 words
#define STG_W (AW + BW)               // 6400 words = 25600 B
#define NSTG 3
#define SMEM1_BYTES (NSTG * STG_W * 4)  // 76800

// Scratch (device globals; zero-initialized at load)
__device__ __half g_K[(size_t)NQ * MP];
__device__ __half g_Wt[(size_t)YY * MP];
__device__ __half g_Xh[(size_t)NQ * DD];
__device__ __half g_Zh[(size_t)MP * DD];
__device__ float  g_xsq[NQ];
__device__ float  g_zsq[MP];

// ---------------------------------------------------------------------------
// Helpers
// ---------------------------------------------------------------------------
__device__ __forceinline__ void mma_f16_f32(float* c, const uint32_t* a, const uint32_t* b) {
    asm volatile(
        "mma.sync.aligned.m16n8k16.row.col.f32.f16.f16.f32 "
        "{%0,%1,%2,%3},{%4,%5,%6,%7},{%8,%9},{%0,%1,%2,%3};"
        : "+f"(c[0]), "+f"(c[1]), "+f"(c[2]), "+f"(c[3])
        : "r"(a[0]), "r"(a[1]), "r"(a[2]), "r"(a[3]), "r"(b[0]), "r"(b[1]));
}

__device__ __forceinline__ void mma_f16_f16(uint32_t* c, const uint32_t* a, const uint32_t* b) {
    asm volatile(
        "mma.sync.aligned.m16n8k16.row.col.f16.f16.f16.f16 "
        "{%0,%1},{%2,%3,%4,%5},{%6,%7},{%0,%1};"
        : "+r"(c[0]), "+r"(c[1])
        : "r"(a[0]), "r"(a[1]), "r"(a[2]), "r"(a[3]), "r"(b[0]), "r"(b[1]));
}

__device__ __forceinline__ uint32_t smem_u32(const void* p) {
    uint32_t a;
    asm("{ .reg .u64 t; cvta.to.shared.u64 t, %1; cvt.u32.u64 %0, t; }" : "=r"(a) : "l"(p));
    return a;
}

__device__ __forceinline__ void cp_async16(uint32_t dst, const void* src) {
    asm volatile("cp.async.cg.shared.global [%0], [%1], 16;" :: "r"(dst), "l"(src));
}
__device__ __forceinline__ void cpa_commit() { asm volatile("cp.async.commit_group;" ::: "memory"); }
__device__ __forceinline__ void cpa_wait1()  { asm volatile("cp.async.wait_group 1;" ::: "memory"); }
__device__ __forceinline__ void cpa_wait0()  { asm volatile("cp.async.wait_group 0;" ::: "memory"); }

__device__ __forceinline__ uint32_t h2u(__half2 h) { return *reinterpret_cast<uint32_t*>(&h); }

__device__ __forceinline__ float resolve_bw(const void* p) {
    int iv = *(const int*)p;
    if (iv > 0 && iv < 1000000) return (float)iv;
    return *(const float*)p;
}

// ---------------------------------------------------------------------------
// Kernel 0: convert fp32 rows -> fp16 AND exact fp32 row sq-norms.
// ---------------------------------------------------------------------------
__global__ void convert_kernel(const float* __restrict__ x, const float* __restrict__ z) {
    int gwarp = (blockIdx.x * blockDim.x + threadIdx.x) >> 5;
    int lane = threadIdx.x & 31;
    const float* src;
    __half* dh;
    float* dsq;
    if (gwarp < NQ) {
        src = x + (size_t)gwarp * DD; dh = g_Xh + (size_t)gwarp * DD; dsq = g_xsq + gwarp;
    } else if (gwarp < NQ + MC) {
        int r = gwarp - NQ;
        src = z + (size_t)r * DD;     dh = g_Zh + (size_t)r * DD;     dsq = g_zsq + r;
    } else return;

    const float4* p = (const float4*)src;
    uint2* o = (uint2*)dh;
    float s = 0.f;
#pragma unroll
    for (int i = 0; i < DD / 128; i++) {
        float4 v = p[lane + i * 32];
        s += v.x * v.x + v.y * v.y + v.z * v.z + v.w * v.w;
        o[lane + i * 32] = make_uint2(h2u(__floats2half2_rn(v.x, v.y)),
                                      h2u(__floats2half2_rn(v.z, v.w)));
    }
#pragma unroll
    for (int off = 16; off; off >>= 1) s += __shfl_xor_sync(0xffffffffu, s, off);
    if (lane == 0) *dsq = s;
}

// ---------------------------------------------------------------------------
// Kernel 0b: transpose W [MC, YY] fp32 -> g_Wt [YY, MP] fp16
// ---------------------------------------------------------------------------
__global__ void wtrans_kernel(const float* __restrict__ W) {
    __shared__ float t[32][33];
    const int k0 = blockIdx.x * 32;
    const int n0 = blockIdx.y * 32;
    const int tx = threadIdx.x, ty = threadIdx.y;
    t[ty][tx] = W[(size_t)(k0 + ty) * YY + (n0 + tx)];
    __syncthreads();
    g_Wt[(size_t)(n0 + ty) * MP + (k0 + tx)] = __float2half_rn(t[tx][ty]);
}

// ---------------------------------------------------------------------------
// Kernel 1: heterogeneous pipe GEMM.
//   warps 0-3 : 128x128 tile via HMMA (tensor pipe), warp tile 64x64, f16 acc
//   warps 4-7 : 64x128 tile via HFMA2 (fma pipe), rows 128..191
// Both share the B stage. BK=32, cp.async 3-stage ring. Grid (43, 157).
// ---------------------------------------------------------------------------
__global__ __launch_bounds__(256)
void laplace_gemm_kernel(const void* __restrict__ bwp) {
    extern __shared__ uint32_t smw[];   // NSTG stages: [A 192x20w][B 128x20w]
    const uint32_t sb0 = smem_u32(smw);

    const int bm = blockIdx.x;      // 0..42
    const int bn = blockIdx.y;      // 0..156
    const int tid = threadIdx.x;    // 0..255
    const int lane = tid & 31;
    const int wid = tid >> 5;       // 0..7

    // Staging: threads 0..191 stage A row tid; threads 128..255 stage B row tid-128.
    int arow_g = bm * BMALL + tid;
    if (arow_g > NQ - 1) arow_g = NQ - 1;               // clamp (last CTA SIMT overrun)
    const __half* xg = g_Xh + (size_t)arow_g * DD;
    const __half* zg = g_Zh + (size_t)(bn * BN1 + (tid & 127)) * DD;
    const uint32_t a_dst = (uint32_t)tid * (ROWW * 4);
    const uint32_t b_dst = AW * 4 + (uint32_t)(tid & 127) * (ROWW * 4);
    const bool doA = (tid < BMALL);
    const bool doB = (tid >= 128);

    const int KT = DD / 32;   // 32

    auto issue = [&](int kt, int s) {
        const uint32_t sb = sb0 + (uint32_t)s * (STG_W * 4);
        if (doA) {
            const char* ag = (const char*)(xg + kt * 32);
#pragma unroll
            for (int j = 0; j < 4; j++) cp_async16(sb + a_dst + j * 16, ag + j * 16);
        }
        if (doB) {
            const char* bg = (const char*)(zg + kt * 32);
#pragma unroll
            for (int j = 0; j < 4; j++) cp_async16(sb + b_dst + j * 16, bg + j * 16);
        }
        cpa_commit();
    };

    issue(0, 0);
    issue(1, 1);

    const float inv_bw = 1.0f / resolve_bw(bwp);

    if (wid < 4) {
        // ----------------- tensor warps: 128x128 HMMA tile -----------------
        const int wm = (wid & 1) * 64;
        const int wn = (wid >> 1) * 64;
        const int frow = lane >> 2;
        const int kbase = lane & 3;

        uint32_t acc[4][8][2];
#pragma unroll
        for (int mt = 0; mt < 4; mt++)
#pragma unroll
            for (int nt = 0; nt < 8; nt++) { acc[mt][nt][0] = 0u; acc[mt][nt][1] = 0u; }

        for (int kt = 0; kt < KT; kt++) {
            if (kt < KT - 1) cpa_wait1(); else cpa_wait0();
            __syncthreads();
            if (kt + 2 < KT) issue(kt + 2, (kt + 2) % NSTG);

            const uint32_t* sa = smw + (size_t)(kt % NSTG) * STG_W;
            const uint32_t* sbp = sa + AW;

#pragma unroll
            for (int kk = 0; kk < 2; kk++) {
                const int kw = kk * 8 + kbase;
                uint32_t a[4][4], b[8][2];
#pragma unroll
                for (int mt = 0; mt < 4; mt++) {
                    const int r = wm + mt * 16 + frow;
                    a[mt][0] = sa[r * ROWW + kw];
                    a[mt][1] = sa[(r + 8) * ROWW + kw];
                    a[mt][2] = sa[r * ROWW + kw + 4];
                    a[mt][3] = sa[(r + 8) * ROWW + kw + 4];
                }
#pragma unroll
                for (int nt = 0; nt < 8; nt++) {
                    const int c = wn + nt * 8 + frow;
                    b[nt][0] = sbp[c * ROWW + kw];
                    b[nt][1] = sbp[c * ROWW + kw + 4];
                }
#pragma unroll
                for (int mt = 0; mt < 4; mt++)
#pragma unroll
                    for (int nt = 0; nt < 8; nt++)
                        mma_f16_f16(acc[mt][nt], a[mt], b[nt]);
            }
            __syncthreads();
        }

        // epilogue (tensor rows always < NQ)
#pragma unroll
        for (int mt = 0; mt < 4; mt++) {
            const int r0 = bm * BMALL + wm + mt * 16 + frow;
            const float xs0 = g_xsq[r0];
            const float xs1 = g_xsq[r0 + 8];
#pragma unroll
            for (int nt = 0; nt < 8; nt++) {
                const int c0 = bn * BN1 + wn + nt * 8 + (kbase << 1);
                const float zs0 = g_zsq[c0];
                const float zs1 = g_zsq[c0 + 1];
                float2 v0 = __half22float2(*(__half2*)&acc[mt][nt][0]);
                float2 v1 = __half22float2(*(__half2*)&acc[mt][nt][1]);
                float f0 = __expf(-sqrtf(fmaxf(xs0 + zs0 - 2.f * v0.x, 0.f)) * inv_bw);
                float f1 = __expf(-sqrtf(fmaxf(xs0 + zs1 - 2.f * v0.y, 0.f)) * inv_bw);
                *(__half2*)&g_K[(size_t)r0 * MP + c0] = __floats2half2_rn(f0, f1);
                f0 = __expf(-sqrtf(fmaxf(xs1 + zs0 - 2.f * v1.x, 0.f)) * inv_bw);
                f1 = __expf(-sqrtf(fmaxf(xs1 + zs1 - 2.f * v1.y, 0.f)) * inv_bw);
                *(__half2*)&g_K[(size_t)(r0 + 8) * MP + c0] = __floats2half2_rn(f0, f1);
            }
        }
    } else {
        // ----------------- SIMT warps: 64x128 HFMA2 tile -------------------
        const int sw = wid - 4;                       // 0..3
        const int r0l = BMT + sw * 16 + (lane >> 3) * 4;   // local A row base (4 rows)
        const int c0 = lane & 7;                      // col base; cols c0 + 8j, j=0..15

        __half2 acc2[4][16];
        const __half2 hz = __float2half2_rn(0.f);
#pragma unroll
        for (int i = 0; i < 4; i++)
#pragma unroll
            for (int j = 0; j < 16; j++) acc2[i][j] = hz;

        for (int kt = 0; kt < KT; kt++) {
            if (kt < KT - 1) cpa_wait1(); else cpa_wait0();
            __syncthreads();
            if (kt + 2 < KT) issue(kt + 2, (kt + 2) % NSTG);

            const uint32_t* sa = smw + (size_t)(kt % NSTG) * STG_W;
            const uint32_t* sbp = sa + AW;

#pragma unroll 4
            for (int w = 0; w < 16; w++) {            // 16 k-pairs in this kt
                uint32_t xw[4], zw[16];
#pragma unroll
                for (int i = 0; i < 4; i++) xw[i] = sa[(r0l + i) * ROWW + w];
#pragma unroll
                for (int j = 0; j < 16; j++) zw[j] = sbp[(c0 + 8 * j) * ROWW + w];
#pragma unroll
                for (int i = 0; i < 4; i++) {
                    __half2 xv = *reinterpret_cast<__half2*>(&xw[i]);
#pragma unroll
                    for (int j = 0; j < 16; j++) {
                        __half2 zv = *reinterpret_cast<__half2*>(&zw[j]);
                        acc2[i][j] = __hfma2(xv, zv, acc2[i][j]);
                    }
                }
            }
            __syncthreads();
        }

        // epilogue (guard rows >= NQ on last CTA)
#pragma unroll
        for (int i = 0; i < 4; i++) {
            const int m = bm * BMALL + BMT + sw * 16 + (lane >> 3) * 4 + i;
            if (m < NQ) {
                const float xs = g_xsq[m];
                __half* krow = g_K + (size_t)m * MP + bn * BN1;
#pragma unroll
                for (int j = 0; j < 16; j++) {
                    const int c = c0 + 8 * j;
                    float2 v = __half22float2(acc2[i][j]);
                    float dot = v.x + v.y;
                    float d2 = xs + g_zsq[bn * BN1 + c] - 2.f * dot;
                    krow[c] = __float2half_rn(__expf(-sqrtf(fmaxf(d2, 0.f)) * inv_bw));
                }
            }
        }
    }
}

// ---------------------------------------------------------------------------
// Kernel 2: pred = K @ W (unchanged R12 config).
// ---------------------------------------------------------------------------
__global__ __launch_bounds__(128, 4)
void wgemm_kernel(float* __restrict__ out) {
    __shared__ uint32_t As[2][32][PADW];
    __shared__ uint32_t Bs[2][128][PADW];

    const int bm = blockIdx.x;
    const int bn = blockIdx.y;
    const int tid = threadIdx.x;
    const int lane = tid & 31;
    const int wid = tid >> 5;
    const int wn = wid * 32;

    float acc[2][4][4];
#pragma unroll
    for (int mt = 0; mt < 2; mt++)
#pragma unroll
        for (int nt = 0; nt < 4; nt++)
#pragma unroll
            for (int i = 0; i < 4; i++) acc[mt][nt][i] = 0.f;

    const int alr = tid >> 2;
    const int awo = (tid & 3) * 4;
    const size_t abase = (size_t)(bm * 32 + alr) * MP + awo * 2;
    const size_t bbase = (size_t)(bn * 128 + tid) * MP;

    uint4 ua = *(const uint4*)(g_K + abase);
    uint4 ub[4];
#pragma unroll
    for (int j = 0; j < 4; j++) ub[j] = *(const uint4*)(g_Wt + bbase + j * 8);
    *(uint4*)&As[0][alr][awo] = ua;
#pragma unroll
    for (int j = 0; j < 4; j++) *(uint4*)&Bs[0][tid][j * 4] = ub[j];
    __syncthreads();

    const int KT = MP / 32;
    for (int kt = 0; kt < KT; kt++) {
        const int buf = kt & 1;
        if (kt + 1 < KT) {
            const size_t off = (size_t)(kt + 1) * 32;
            ua = *(const uint4*)(g_K + abase + off);
#pragma unroll
            for (int j = 0; j < 4; j++) ub[j] = *(const uint4*)(g_Wt + bbase + off + j * 8);
        }

#pragma unroll
        for (int kk = 0; kk < 2; kk++) {
            const int kw = kk * 8 + (lane & 3);
            const int frow = lane >> 2;
            uint32_t a[2][4], b[4][2];
#pragma unroll
            for (int mt = 0; mt < 2; mt++) {
                int r = mt * 16 + frow;
                a[mt][0] = As[buf][r][kw];
                a[mt][1] = As[buf][r + 8][kw];
                a[mt][2] = As[buf][r][kw + 4];
                a[mt][3] = As[buf][r + 8][kw + 4];
            }
#pragma unroll
            for (int nt = 0; nt < 4; nt++) {
                int c = wn + nt * 8 + frow;
                b[nt][0] = Bs[buf][c][kw];
                b[nt][1] = Bs[buf][c][kw + 4];
            }
#pragma unroll
            for (int mt = 0; mt < 2; mt++)
#pragma unroll
                for (int nt = 0; nt < 4; nt++)
                    mma_f16_f32(acc[mt][nt], a[mt], b[nt]);
        }

        if (kt + 1 < KT) {
            const int nb = buf ^ 1;
            *(uint4*)&As[nb][alr][awo] = ua;
#pragma unroll
            for (int j = 0; j < 4; j++) *(uint4*)&Bs[nb][tid][j * 4] = ub[j];
        }
        __syncthreads();
    }

#pragma unroll
    for (int mt = 0; mt < 2; mt++) {
        const int r0 = bm * 32 + mt * 16 + (lane >> 2);
#pragma unroll
        for (int nt = 0; nt < 4; nt++) {
            const int c0 = bn * 128 + wn + nt * 8 + ((lane & 3) << 1);
            *(float2*)(out + (size_t)r0 * YY + c0) =
                make_float2(acc[mt][nt][0], acc[mt][nt][1]);
            *(float2*)(out + (size_t)(r0 + 8) * YY + c0) =
                make_float2(acc[mt][nt][2], acc[mt][nt][3]);
        }
    }
}

// ---------------------------------------------------------------------------
// Entry point
// ---------------------------------------------------------------------------
extern "C" void kernel_launch(void* const* d_in, const int* in_sizes, int n_in,
                              void* d_out, int out_size) {
    const float* batch   = (const float*)d_in[0];
    const float* centers = (const float*)d_in[1];
    const float* weight  = (const float*)d_in[2];
    const void*  bwp     = d_in[3];

    {
        int warps = NQ + MC;
        int blocks = (warps * 32 + 255) / 256;
        convert_kernel<<<blocks, 256>>>(batch, centers);
    }
    {
        dim3 grid(MC / 32, YY / 32);
        wtrans_kernel<<<grid, dim3(32, 32)>>>(weight);
    }
    {
        static bool attr_set = false;
        if (!attr_set) {
            cudaFuncSetAttribute(laplace_gemm_kernel,
                                 cudaFuncAttributeMaxDynamicSharedMemorySize, SMEM1_BYTES);
            attr_set = true;
        }
        dim3 grid((NQ + BMALL - 1) / BMALL, (MC + BN1 - 1) / BN1);  // (43, 157)
        laplace_gemm_kernel<<<grid, 256, SMEM1_BYTES>>>(bwp);
    }
    {
        dim3 grid(NQ / 32, YY / 128);
        wgemm_kernel<<<grid, 128>>>((float*)d_out);
    }
}

// round 16
// speedup vs baseline: 1.1346x; 1.1346x over previous
#include <cuda_runtime.h>
#include <cuda_fp16.h>
#include <cstdint>
#include <cstddef>

// Problem dims
#define NQ 8192
#define MC 20000
#define MP 20096            // centers padded: 157*128
#define DD 1024
#define YY 256
#define PADW 20             // smem row stride words (conflict-free walk)

// Scratch (device globals; zero-initialized at load)
__device__ __half g_K[(size_t)NQ * MP];    // fp16 kernel matrix
__device__ __half g_Wt[(size_t)YY * MP];   // W transposed, k-contiguous; tail 0
__device__ __half g_Xh[(size_t)NQ * DD];   // fp16 batch
__device__ __half g_Zh[(size_t)MP * DD];   // fp16 centers; tail rows stay 0
__device__ float  g_xsq[NQ];
__device__ float  g_zsq[MP];               // tail stays 0

// ---------------------------------------------------------------------------
// Helpers
// ---------------------------------------------------------------------------
__device__ __forceinline__ void mma_f16_f32(float* c, const uint32_t* a, const uint32_t* b) {
    asm volatile(
        "mma.sync.aligned.m16n8k16.row.col.f32.f16.f16.f32 "
        "{%0,%1,%2,%3},{%4,%5,%6,%7},{%8,%9},{%0,%1,%2,%3};"
        : "+f"(c[0]), "+f"(c[1]), "+f"(c[2]), "+f"(c[3])
        : "r"(a[0]), "r"(a[1]), "r"(a[2]), "r"(a[3]), "r"(b[0]), "r"(b[1]));
}

__device__ __forceinline__ uint32_t h2u(__half2 h) { return *reinterpret_cast<uint32_t*>(&h); }

__device__ __forceinline__ float resolve_bw(const void* p) {
    int iv = *(const int*)p;
    if (iv > 0 && iv < 1000000) return (float)iv;
    return *(const float*)p;
}

// ---------------------------------------------------------------------------
// Kernel 0: convert fp32 rows -> fp16 AND exact fp32 row sq-norms.
// ---------------------------------------------------------------------------
__global__ void convert_kernel(const float* __restrict__ x, const float* __restrict__ z) {
    int gwarp = (blockIdx.x * blockDim.x + threadIdx.x) >> 5;
    int lane = threadIdx.x & 31;
    const float* src;
    __half* dh;
    float* dsq;
    if (gwarp < NQ) {
        src = x + (size_t)gwarp * DD; dh = g_Xh + (size_t)gwarp * DD; dsq = g_xsq + gwarp;
    } else if (gwarp < NQ + MC) {
        int r = gwarp - NQ;
        src = z + (size_t)r * DD;     dh = g_Zh + (size_t)r * DD;     dsq = g_zsq + r;
    } else return;

    const float4* p = (const float4*)src;
    uint2* o = (uint2*)dh;
    float s = 0.f;
#pragma unroll
    for (int i = 0; i < DD / 128; i++) {
        float4 v = p[lane + i * 32];
        s += v.x * v.x + v.y * v.y + v.z * v.z + v.w * v.w;
        o[lane + i * 32] = make_uint2(h2u(__floats2half2_rn(v.x, v.y)),
                                      h2u(__floats2half2_rn(v.z, v.w)));
    }
#pragma unroll
    for (int off = 16; off; off >>= 1) s += __shfl_xor_sync(0xffffffffu, s, off);
    if (lane == 0) *dsq = s;
}

// ---------------------------------------------------------------------------
// Kernel 0b: transpose W [MC, YY] fp32 -> g_Wt [YY, MP] fp16
// ---------------------------------------------------------------------------
__global__ void wtrans_kernel(const float* __restrict__ W) {
    __shared__ float t[32][33];
    const int k0 = blockIdx.x * 32;
    const int n0 = blockIdx.y * 32;
    const int tx = threadIdx.x, ty = threadIdx.y;
    t[ty][tx] = W[(size_t)(k0 + ty) * YY + (n0 + tx)];
    __syncthreads();
    g_Wt[(size_t)(n0 + ty) * MP + (k0 + tx)] = __float2half_rn(t[tx][ty]);
}

// ---------------------------------------------------------------------------
// Kernel 1: K[i,j] = exp(-sqrt(max(xsq+zsq-2*X.Z,0))/bw), fp16 out.
// Rebuilt in the wgemm shape (best measured legacy-HMMA rate): BM=BN=64,
// BK=32, 128 threads, 4 warps at 32x32 warp tiles, f32 accumulators,
// register-staged double buffer, 4 CTAs/SM. Grid (128, 314).
// ---------------------------------------------------------------------------
__global__ __launch_bounds__(128, 4)
void laplace_gemm_kernel(const void* __restrict__ bwp) {
    __shared__ uint32_t As[2][64][PADW];
    __shared__ uint32_t Bs[2][64][PADW];

    const int bm = blockIdx.x;   // 0..127  (batch row block)
    const int bn = blockIdx.y;   // 0..313  (center block)
    const int tid = threadIdx.x;
    const int lane = tid & 31;
    const int wid = tid >> 5;    // 0..3
    const int wm = (wid & 1) * 32;
    const int wn = (wid >> 1) * 32;

    float acc[2][4][4];
#pragma unroll
    for (int mt = 0; mt < 2; mt++)
#pragma unroll
        for (int nt = 0; nt < 4; nt++)
#pragma unroll
            for (int i = 0; i < 4; i++) acc[mt][nt][i] = 0.f;

    // Staging: 64 rows x 16 words each for A and B; 2 threads per row,
    // each thread owns 8 words (2 uint4) of one A row and one B row.
    const int slr = tid >> 1;            // 0..63
    const int swo = (tid & 1) * 8;       // word offset 0 or 8
    const __half* ag = g_Xh + (size_t)(bm * 64 + slr) * DD + swo * 2;
    const __half* bg = g_Zh + (size_t)(bn * 64 + slr) * DD + swo * 2;

    // Prologue: tile 0
    uint4 ua0 = *(const uint4*)(ag);
    uint4 ua1 = *(const uint4*)(ag + 8);
    uint4 ub0 = *(const uint4*)(bg);
    uint4 ub1 = *(const uint4*)(bg + 8);
    *(uint4*)&As[0][slr][swo] = ua0;  *(uint4*)&As[0][slr][swo + 4] = ua1;
    *(uint4*)&Bs[0][slr][swo] = ub0;  *(uint4*)&Bs[0][slr][swo + 4] = ub1;
    __syncthreads();

    const int KT = DD / 32;   // 32
    for (int kt = 0; kt < KT; kt++) {
        const int buf = kt & 1;
        if (kt + 1 < KT) {
            const size_t off = (size_t)(kt + 1) * 32;
            ua0 = *(const uint4*)(ag + off);
            ua1 = *(const uint4*)(ag + off + 8);
            ub0 = *(const uint4*)(bg + off);
            ub1 = *(const uint4*)(bg + off + 8);
        }

#pragma unroll
        for (int kk = 0; kk < 2; kk++) {
            const int kw = kk * 8 + (lane & 3);
            const int frow = lane >> 2;
            uint32_t a[2][4], b[4][2];
#pragma unroll
            for (int mt = 0; mt < 2; mt++) {
                int r = wm + mt * 16 + frow;
                a[mt][0] = As[buf][r][kw];
                a[mt][1] = As[buf][r + 8][kw];
                a[mt][2] = As[buf][r][kw + 4];
                a[mt][3] = As[buf][r + 8][kw + 4];
            }
#pragma unroll
            for (int nt = 0; nt < 4; nt++) {
                int c = wn + nt * 8 + frow;
                b[nt][0] = Bs[buf][c][kw];
                b[nt][1] = Bs[buf][c][kw + 4];
            }
#pragma unroll
            for (int mt = 0; mt < 2; mt++)
#pragma unroll
                for (int nt = 0; nt < 4; nt++)
                    mma_f16_f32(acc[mt][nt], a[mt], b[nt]);
        }

        if (kt + 1 < KT) {
            const int nb = buf ^ 1;
            *(uint4*)&As[nb][slr][swo] = ua0;  *(uint4*)&As[nb][slr][swo + 4] = ua1;
            *(uint4*)&Bs[nb][slr][swo] = ub0;  *(uint4*)&Bs[nb][slr][swo + 4] = ub1;
        }
        __syncthreads();
    }

    // Epilogue: d2 -> exp(-d/bw) -> g_K (fp16). Padded cols get garbage
    // (zs=0, Zh=0 rows) but wgemm multiplies them by Wt zeros — harmless.
    const float inv_bw = 1.0f / resolve_bw(bwp);
#pragma unroll
    for (int mt = 0; mt < 2; mt++) {
        const int r0 = bm * 64 + wm + mt * 16 + (lane >> 2);
        const float xs0 = g_xsq[r0];
        const float xs1 = g_xsq[r0 + 8];
#pragma unroll
        for (int nt = 0; nt < 4; nt++) {
            const int c0 = bn * 64 + wn + nt * 8 + ((lane & 3) << 1);
            const float zs0 = g_zsq[c0];
            const float zs1 = g_zsq[c0 + 1];
            float f0 = __expf(-sqrtf(fmaxf(xs0 + zs0 - 2.f * acc[mt][nt][0], 0.f)) * inv_bw);
            float f1 = __expf(-sqrtf(fmaxf(xs0 + zs1 - 2.f * acc[mt][nt][1], 0.f)) * inv_bw);
            *(__half2*)&g_K[(size_t)r0 * MP + c0] = __floats2half2_rn(f0, f1);
            f0 = __expf(-sqrtf(fmaxf(xs1 + zs0 - 2.f * acc[mt][nt][2], 0.f)) * inv_bw);
            f1 = __expf(-sqrtf(fmaxf(xs1 + zs1 - 2.f * acc[mt][nt][3], 0.f)) * inv_bw);
            *(__half2*)&g_K[(size_t)(r0 + 8) * MP + c0] = __floats2half2_rn(f0, f1);
        }
    }
}

// ---------------------------------------------------------------------------
// Kernel 2: pred = K @ W (unchanged R12 config: best measured).
// ---------------------------------------------------------------------------
__global__ __launch_bounds__(128, 4)
void wgemm_kernel(float* __restrict__ out) {
    __shared__ uint32_t As[2][32][PADW];
    __shared__ uint32_t Bs[2][128][PADW];

    const int bm = blockIdx.x;
    const int bn = blockIdx.y;
    const int tid = threadIdx.x;
    const int lane = tid & 31;
    const int wid = tid >> 5;
    const int wn = wid * 32;

    float acc[2][4][4];
#pragma unroll
    for (int mt = 0; mt < 2; mt++)
#pragma unroll
        for (int nt = 0; nt < 4; nt++)
#pragma unroll
            for (int i = 0; i < 4; i++) acc[mt][nt][i] = 0.f;

    const int alr = tid >> 2;
    const int awo = (tid & 3) * 4;
    const size_t abase = (size_t)(bm * 32 + alr) * MP + awo * 2;
    const size_t bbase = (size_t)(bn * 128 + tid) * MP;

    uint4 ua = *(const uint4*)(g_K + abase);
    uint4 ub[4];
#pragma unroll
    for (int j = 0; j < 4; j++) ub[j] = *(const uint4*)(g_Wt + bbase + j * 8);
    *(uint4*)&As[0][alr][awo] = ua;
#pragma unroll
    for (int j = 0; j < 4; j++) *(uint4*)&Bs[0][tid][j * 4] = ub[j];
    __syncthreads();

    const int KT = MP / 32;
    for (int kt = 0; kt < KT; kt++) {
        const int buf = kt & 1;
        if (kt + 1 < KT) {
            const size_t off = (size_t)(kt + 1) * 32;
            ua = *(const uint4*)(g_K + abase + off);
#pragma unroll
            for (int j = 0; j < 4; j++) ub[j] = *(const uint4*)(g_Wt + bbase + off + j * 8);
        }

#pragma unroll
        for (int kk = 0; kk < 2; kk++) {
            const int kw = kk * 8 + (lane & 3);
            const int frow = lane >> 2;
            uint32_t a[2][4], b[4][2];
#pragma unroll
            for (int mt = 0; mt < 2; mt++) {
                int r = mt * 16 + frow;
                a[mt][0] = As[buf][r][kw];
                a[mt][1] = As[buf][r + 8][kw];
                a[mt][2] = As[buf][r][kw + 4];
                a[mt][3] = As[buf][r + 8][kw + 4];
            }
#pragma unroll
            for (int nt = 0; nt < 4; nt++) {
                int c = wn + nt * 8 + frow;
                b[nt][0] = Bs[buf][c][kw];
                b[nt][1] = Bs[buf][c][kw + 4];
            }
#pragma unroll
            for (int mt = 0; mt < 2; mt++)
#pragma unroll
                for (int nt = 0; nt < 4; nt++)
                    mma_f16_f32(acc[mt][nt], a[mt], b[nt]);
        }

        if (kt + 1 < KT) {
            const int nb = buf ^ 1;
            *(uint4*)&As[nb][alr][awo] = ua;
#pragma unroll
            for (int j = 0; j < 4; j++) *(uint4*)&Bs[nb][tid][j * 4] = ub[j];
        }
        __syncthreads();
    }

#pragma unroll
    for (int mt = 0; mt < 2; mt++) {
        const int r0 = bm * 32 + mt * 16 + (lane >> 2);
#pragma unroll
        for (int nt = 0; nt < 4; nt++) {
            const int c0 = bn * 128 + wn + nt * 8 + ((lane & 3) << 1);
            *(float2*)(out + (size_t)r0 * YY + c0) =
                make_float2(acc[mt][nt][0], acc[mt][nt][1]);
            *(float2*)(out + (size_t)(r0 + 8) * YY + c0) =
                make_float2(acc[mt][nt][2], acc[mt][nt][3]);
        }
    }
}

// ---------------------------------------------------------------------------
// Entry point (graph-capturable: launches only)
// ---------------------------------------------------------------------------
extern "C" void kernel_launch(void* const* d_in, const int* in_sizes, int n_in,
                              void* d_out, int out_size) {
    const float* batch   = (const float*)d_in[0];
    const float* centers = (const float*)d_in[1];
    const float* weight  = (const float*)d_in[2];
    const void*  bwp     = d_in[3];

    {
        int warps = NQ + MC;
        int blocks = (warps * 32 + 255) / 256;
        convert_kernel<<<blocks, 256>>>(batch, centers);
    }
    {
        dim3 grid(MC / 32, YY / 32);            // (625, 8)
        wtrans_kernel<<<grid, dim3(32, 32)>>>(weight);
    }
    {
        dim3 grid(NQ / 64, MP / 64);            // (128, 314)
        laplace_gemm_kernel<<<grid, 128>>>(bwp);
    }
    {
        dim3 grid(NQ / 32, YY / 128);           // (256, 2)
        wgemm_kernel<<<grid, 128>>>((float*)d_out);
    }
}

// round 17
// speedup vs baseline: 1.6819x; 1.4824x over previous
#include <cuda_runtime.h>
#include <cuda_fp16.h>
#include <cstdint>
#include <cstddef>

// Problem dims
#define NQ 8192
#define MC 20000
#define MP 20096            // centers padded: 157*128
#define DD 1024
#define YY 256
#define PADW 20             // smem row stride words (conflict-free walk)

// GEMM1 cp.async ring geometry (BM=BN=128, BK=32)
#define ROWW 20
#define HALF_STG (128 * ROWW)           // 2560 words per operand block
#define STG_W (2 * HALF_STG)            // 5120 words = 20480 B per stage
#define NSTG 3
#define SMEM1_BYTES (NSTG * STG_W * 4)  // 61440 B -> 3 CTAs/SM fits 184 KB

// Scratch (device globals; zero-initialized at load)
__device__ __half g_K[(size_t)NQ * MP];    // fp16 kernel matrix
__device__ __half g_Wt[(size_t)YY * MP];   // W transposed, k-contiguous; tail 0
__device__ __half g_Xh[(size_t)NQ * DD];   // fp16 batch
__device__ __half g_Zh[(size_t)MP * DD];   // fp16 centers; tail rows stay 0
__device__ float  g_xsq[NQ];
__device__ float  g_zsq[MP];               // tail stays 0

// ---------------------------------------------------------------------------
// Helpers
// ---------------------------------------------------------------------------
__device__ __forceinline__ void mma_f16_f32(float* c, const uint32_t* a, const uint32_t* b) {
    asm volatile(
        "mma.sync.aligned.m16n8k16.row.col.f32.f16.f16.f32 "
        "{%0,%1,%2,%3},{%4,%5,%6,%7},{%8,%9},{%0,%1,%2,%3};"
        : "+f"(c[0]), "+f"(c[1]), "+f"(c[2]), "+f"(c[3])
        : "r"(a[0]), "r"(a[1]), "r"(a[2]), "r"(a[3]), "r"(b[0]), "r"(b[1]));
}

__device__ __forceinline__ void mma_f16_f16(uint32_t* c, const uint32_t* a, const uint32_t* b) {
    asm volatile(
        "mma.sync.aligned.m16n8k16.row.col.f16.f16.f16.f16 "
        "{%0,%1},{%2,%3,%4,%5},{%6,%7},{%0,%1};"
        : "+r"(c[0]), "+r"(c[1])
        : "r"(a[0]), "r"(a[1]), "r"(a[2]), "r"(a[3]), "r"(b[0]), "r"(b[1]));
}

__device__ __forceinline__ uint32_t smem_u32(const void* p) {
    uint32_t a;
    asm("{ .reg .u64 t; cvta.to.shared.u64 t, %1; cvt.u32.u64 %0, t; }" : "=r"(a) : "l"(p));
    return a;
}

__device__ __forceinline__ void cp_async16(uint32_t dst, const void* src) {
    asm volatile("cp.async.cg.shared.global [%0], [%1], 16;" :: "r"(dst), "l"(src));
}
__device__ __forceinline__ void cpa_commit() { asm volatile("cp.async.commit_group;" ::: "memory"); }
__device__ __forceinline__ void cpa_wait1()  { asm volatile("cp.async.wait_group 1;" ::: "memory"); }
__device__ __forceinline__ void cpa_wait0()  { asm volatile("cp.async.wait_group 0;" ::: "memory"); }

__device__ __forceinline__ uint32_t h2u(__half2 h) { return *reinterpret_cast<uint32_t*>(&h); }

__device__ __forceinline__ float resolve_bw(const void* p) {
    int iv = *(const int*)p;
    if (iv > 0 && iv < 1000000) return (float)iv;
    return *(const float*)p;
}

// ---------------------------------------------------------------------------
// Kernel 0: convert fp32 rows -> fp16 AND exact fp32 row sq-norms.
// ---------------------------------------------------------------------------
__global__ void convert_kernel(const float* __restrict__ x, const float* __restrict__ z) {
    int gwarp = (blockIdx.x * blockDim.x + threadIdx.x) >> 5;
    int lane = threadIdx.x & 31;
    const float* src;
    __half* dh;
    float* dsq;
    if (gwarp < NQ) {
        src = x + (size_t)gwarp * DD; dh = g_Xh + (size_t)gwarp * DD; dsq = g_xsq + gwarp;
    } else if (gwarp < NQ + MC) {
        int r = gwarp - NQ;
        src = z + (size_t)r * DD;     dh = g_Zh + (size_t)r * DD;     dsq = g_zsq + r;
    } else return;

    const float4* p = (const float4*)src;
    uint2* o = (uint2*)dh;
    float s = 0.f;
#pragma unroll
    for (int i = 0; i < DD / 128; i++) {
        float4 v = p[lane + i * 32];
        s += v.x * v.x + v.y * v.y + v.z * v.z + v.w * v.w;
        o[lane + i * 32] = make_uint2(h2u(__floats2half2_rn(v.x, v.y)),
                                      h2u(__floats2half2_rn(v.z, v.w)));
    }
#pragma unroll
    for (int off = 16; off; off >>= 1) s += __shfl_xor_sync(0xffffffffu, s, off);
    if (lane == 0) *dsq = s;
}

// ---------------------------------------------------------------------------
// Kernel 0b: transpose W [MC, YY] fp32 -> g_Wt [YY, MP] fp16
// ---------------------------------------------------------------------------
__global__ void wtrans_kernel(const float* __restrict__ W) {
    __shared__ float t[32][33];
    const int k0 = blockIdx.x * 32;
    const int n0 = blockIdx.y * 32;
    const int tx = threadIdx.x, ty = threadIdx.y;
    t[ty][tx] = W[(size_t)(k0 + ty) * YY + (n0 + tx)];
    __syncthreads();
    g_Wt[(size_t)(n0 + ty) * MP + (k0 + tx)] = __float2half_rn(t[tx][ty]);
}

// ---------------------------------------------------------------------------
// Kernel 1: K[i,j] = exp(-sqrt(max(xsq+zsq-2*X.Z,0))/bw), fp16 out.
// R12 geometry (BM=BN=128, BK=32, 8 warps, 64x32 warp tile, f16 acc) but with
// a cp.async 3-stage ring (no staging registers) and 3 CTAs/SM. Grid (64,157).
// ---------------------------------------------------------------------------
__global__ __launch_bounds__(256, 3)
void laplace_gemm_kernel(const void* __restrict__ bwp) {
    extern __shared__ uint32_t smw[];   // NSTG stages: [X 128x20w][Z 128x20w]
    const uint32_t sb0 = smem_u32(smw);

    const int bm = blockIdx.x;      // 0..63
    const int bn = blockIdx.y;      // 0..156
    const int tid = threadIdx.x;
    const int lane = tid & 31;
    const int wid = tid >> 5;
    const int wm = (wid & 1) * 64;
    const int wn = (wid >> 1) * 32;

    uint32_t acc[4][4][2];          // f16x2 accumulators
#pragma unroll
    for (int mt = 0; mt < 4; mt++)
#pragma unroll
        for (int nt = 0; nt < 4; nt++) { acc[mt][nt][0] = 0u; acc[mt][nt][1] = 0u; }

    // Staging: thread covers 32B (2x16B) of one X row and one Z row per kt.
    const int lr = tid >> 1;               // 0..127
    const int hs = (tid & 1);              // half selector
    const __half* xg = g_Xh + (size_t)(bm * 128 + lr) * DD + hs * 16;
    const __half* zg = g_Zh + (size_t)(bn * 128 + lr) * DD + hs * 16;
    const uint32_t a_dst = (uint32_t)(lr * ROWW + hs * 8) * 4;
    const uint32_t b_dst = HALF_STG * 4 + a_dst;

    const int KT = DD / 32;   // 32

    auto issue = [&](int kt, int s) {
        const uint32_t sb = sb0 + (uint32_t)s * (STG_W * 4);
        const char* ag = (const char*)(xg + kt * 32);
        const char* bg = (const char*)(zg + kt * 32);
        cp_async16(sb + a_dst, ag);
        cp_async16(sb + a_dst + 16, ag + 16);
        cp_async16(sb + b_dst, bg);
        cp_async16(sb + b_dst + 16, bg + 16);
        cpa_commit();
    };

    issue(0, 0);
    issue(1, 1);

    const int frow = lane >> 2;
    const int kbase = lane & 3;

    for (int kt = 0; kt < KT; kt++) {
        if (kt < KT - 1) cpa_wait1(); else cpa_wait0();
        __syncthreads();
        if (kt + 2 < KT) issue(kt + 2, (kt + 2) % NSTG);

        const uint32_t* sa = smw + (size_t)(kt % NSTG) * STG_W;
        const uint32_t* sbp = sa + HALF_STG;

#pragma unroll
        for (int kk = 0; kk < 2; kk++) {
            const int kw = kk * 8 + kbase;
            uint32_t a[4][4], b[4][2];
#pragma unroll
            for (int mt = 0; mt < 4; mt++) {
                const int r = wm + mt * 16 + frow;
                a[mt][0] = sa[r * ROWW + kw];
                a[mt][1] = sa[(r + 8) * ROWW + kw];
                a[mt][2] = sa[r * ROWW + kw + 4];
                a[mt][3] = sa[(r + 8) * ROWW + kw + 4];
            }
#pragma unroll
            for (int nt = 0; nt < 4; nt++) {
                const int c = wn + nt * 8 + frow;
                b[nt][0] = sbp[c * ROWW + kw];
                b[nt][1] = sbp[c * ROWW + kw + 4];
            }
#pragma unroll
            for (int mt = 0; mt < 4; mt++)
#pragma unroll
                for (int nt = 0; nt < 4; nt++)
                    mma_f16_f16(acc[mt][nt], a[mt], b[nt]);
        }
        __syncthreads();
    }

    // Epilogue: unpack f16 dot, d2 -> exp(-d/bw) -> g_K (fp16)
    const float inv_bw = 1.0f / resolve_bw(bwp);
#pragma unroll
    for (int mt = 0; mt < 4; mt++) {
        const int r0 = bm * 128 + wm + mt * 16 + frow;
        const float xs0 = g_xsq[r0];
        const float xs1 = g_xsq[r0 + 8];
#pragma unroll
        for (int nt = 0; nt < 4; nt++) {
            const int c0 = bn * 128 + wn + nt * 8 + (kbase << 1);
            const float zs0 = g_zsq[c0];
            const float zs1 = g_zsq[c0 + 1];
            float2 v0 = __half22float2(*(__half2*)&acc[mt][nt][0]);
            float2 v1 = __half22float2(*(__half2*)&acc[mt][nt][1]);
            float f0 = __expf(-sqrtf(fmaxf(xs0 + zs0 - 2.f * v0.x, 0.f)) * inv_bw);
            float f1 = __expf(-sqrtf(fmaxf(xs0 + zs1 - 2.f * v0.y, 0.f)) * inv_bw);
            *(__half2*)&g_K[(size_t)r0 * MP + c0] = __floats2half2_rn(f0, f1);
            f0 = __expf(-sqrtf(fmaxf(xs1 + zs0 - 2.f * v1.x, 0.f)) * inv_bw);
            f1 = __expf(-sqrtf(fmaxf(xs1 + zs1 - 2.f * v1.y, 0.f)) * inv_bw);
            *(__half2*)&g_K[(size_t)(r0 + 8) * MP + c0] = __floats2half2_rn(f0, f1);
        }
    }
}

// ---------------------------------------------------------------------------
// Kernel 2: pred = K @ W (R12 config, unchanged: best measured).
// ---------------------------------------------------------------------------
__global__ __launch_bounds__(128, 4)
void wgemm_kernel(float* __restrict__ out) {
    __shared__ uint32_t As[2][32][PADW];
    __shared__ uint32_t Bs[2][128][PADW];

    const int bm = blockIdx.x;
    const int bn = blockIdx.y;
    const int tid = threadIdx.x;
    const int lane = tid & 31;
    const int wid = tid >> 5;
    const int wn = wid * 32;

    float acc[2][4][4];
#pragma unroll
    for (int mt = 0; mt < 2; mt++)
#pragma unroll
        for (int nt = 0; nt < 4; nt++)
#pragma unroll
            for (int i = 0; i < 4; i++) acc[mt][nt][i] = 0.f;

    const int alr = tid >> 2;
    const int awo = (tid & 3) * 4;
    const size_t abase = (size_t)(bm * 32 + alr) * MP + awo * 2;
    const size_t bbase = (size_t)(bn * 128 + tid) * MP;

    uint4 ua = *(const uint4*)(g_K + abase);
    uint4 ub[4];
#pragma unroll
    for (int j = 0; j < 4; j++) ub[j] = *(const uint4*)(g_Wt + bbase + j * 8);
    *(uint4*)&As[0][alr][awo] = ua;
#pragma unroll
    for (int j = 0; j < 4; j++) *(uint4*)&Bs[0][tid][j * 4] = ub[j];
    __syncthreads();

    const int KT = MP / 32;
    for (int kt = 0; kt < KT; kt++) {
        const int buf = kt & 1;
        if (kt + 1 < KT) {
            const size_t off = (size_t)(kt + 1) * 32;
            ua = *(const uint4*)(g_K + abase + off);
#pragma unroll
            for (int j = 0; j < 4; j++) ub[j] = *(const uint4*)(g_Wt + bbase + off + j * 8);
        }

#pragma unroll
        for (int kk = 0; kk < 2; kk++) {
            const int kw = kk * 8 + (lane & 3);
            const int frow = lane >> 2;
            uint32_t a[2][4], b[4][2];
#pragma unroll
            for (int mt = 0; mt < 2; mt++) {
                int r = mt * 16 + frow;
                a[mt][0] = As[buf][r][kw];
                a[mt][1] = As[buf][r + 8][kw];
                a[mt][2] = As[buf][r][kw + 4];
                a[mt][3] = As[buf][r + 8][kw + 4];
            }
#pragma unroll
            for (int nt = 0; nt < 4; nt++) {
                int c = wn + nt * 8 + frow;
                b[nt][0] = Bs[buf][c][kw];
                b[nt][1] = Bs[buf][c][kw + 4];
            }
#pragma unroll
            for (int mt = 0; mt < 2; mt++)
#pragma unroll
                for (int nt = 0; nt < 4; nt++)
                    mma_f16_f32(acc[mt][nt], a[mt], b[nt]);
        }

        if (kt + 1 < KT) {
            const int nb = buf ^ 1;
            *(uint4*)&As[nb][alr][awo] = ua;
#pragma unroll
            for (int j = 0; j < 4; j++) *(uint4*)&Bs[nb][tid][j * 4] = ub[j];
        }
        __syncthreads();
    }

#pragma unroll
    for (int mt = 0; mt < 2; mt++) {
        const int r0 = bm * 32 + mt * 16 + (lane >> 2);
#pragma unroll
        for (int nt = 0; nt < 4; nt++) {
            const int c0 = bn * 128 + wn + nt * 8 + ((lane & 3) << 1);
            *(float2*)(out + (size_t)r0 * YY + c0) =
                make_float2(acc[mt][nt][0], acc[mt][nt][1]);
            *(float2*)(out + (size_t)(r0 + 8) * YY + c0) =
                make_float2(acc[mt][nt][2], acc[mt][nt][3]);
        }
    }
}

// ---------------------------------------------------------------------------
// Entry point (graph-capturable: launches only)
// ---------------------------------------------------------------------------
extern "C" void kernel_launch(void* const* d_in, const int* in_sizes, int n_in,
                              void* d_out, int out_size) {
    const float* batch   = (const float*)d_in[0];
    const float* centers = (const float*)d_in[1];
    const float* weight  = (const float*)d_in[2];
    const void*  bwp     = d_in[3];

    {
        int warps = NQ + MC;
        int blocks = (warps * 32 + 255) / 256;
        convert_kernel<<<blocks, 256>>>(batch, centers);
    }
    {
        dim3 grid(MC / 32, YY / 32);            // (625, 8)
        wtrans_kernel<<<grid, dim3(32, 32)>>>(weight);
    }
    {
        static bool attr_set = false;
        if (!attr_set) {
            cudaFuncSetAttribute(laplace_gemm_kernel,
                                 cudaFuncAttributeMaxDynamicSharedMemorySize, SMEM1_BYTES);
            attr_set = true;
        }
        dim3 grid(NQ / 128, (MC + 127) / 128);  // (64, 157)
        laplace_gemm_kernel<<<grid, 256, SMEM1_BYTES>>>(bwp);
    }
    {
        dim3 grid(NQ / 32, YY / 128);           // (256, 2)
        wgemm_kernel<<<grid, 128>>>((float*)d_out);
    }
}